// round 5
// baseline (speedup 1.0000x reference)
#include <cuda_runtime.h>

// Problem constants
#define BATCH    8
#define S_BYTES  8192
#define NUM_EMB  384
#define BYTE_DIM 128
#define EMB_DIM  1024
#define NUM_TOK  2048
#define SCALE_F  11.313708498984761f  // sqrt(128)

// proj = SCALE * emb @ W^T : [NUM_EMB, EMB_DIM] fp32 (1.5 MB, L2-resident)
__device__ float g_proj[NUM_EMB * EMB_DIM];
// Segment starts: g_start[b][t] = first byte index s with byte_groups[b][s] >= t
__device__ int g_start[BATCH][NUM_TOK + 1];

// ---------------------------------------------------------------------------
// Kernel 1 (fused): blocks [0,384) tiny GEMM proj = SCALE*emb@W^T,
// blocks [384,640) segment boundaries from sorted byte_groups.
// ---------------------------------------------------------------------------
#define BM 32
#define BN 32
#define SPITCH 33
#define GEMM_BLOCKS 384
#define SEG_BLOCKS  256

__global__ __launch_bounds__(256) void prep_kernel(const float* __restrict__ emb,
                                                   const float* __restrict__ W,
                                                   const int* __restrict__ bg) {
    const int tid = threadIdx.x;

    if (blockIdx.x >= GEMM_BLOCKS) {
        const int blkk = blockIdx.x - GEMM_BLOCKS;
        const int b    = blkk >> 5;
        const int s    = (blkk & 31) * 256 + tid;
        const int* __restrict__ row = bg + (size_t)b * S_BYTES;

        const int g  = row[s];
        const int gp = (s == 0) ? -1 : row[s - 1];
        for (int t = gp + 1; t <= g; ++t) g_start[b][t] = s;
        if (s == S_BYTES - 1) {
            for (int t = g + 1; t <= NUM_TOK; ++t) g_start[b][t] = S_BYTES;
        }
        return;
    }

    __shared__ float As[BYTE_DIM][SPITCH];  // [k][m]
    __shared__ float Ws[BYTE_DIM][SPITCH];  // [k][n]

    const int bn = blockIdx.x & 31;
    const int bm = blockIdx.x >> 5;
    const int tx = tid & 15;
    const int ty = tid >> 4;
    const int m0 = ty * 2;
    const int n0 = tx * 2;

    const float* __restrict__ A  = emb + (size_t)(bm * BM) * BYTE_DIM;
    const float* __restrict__ Wt = W   + (size_t)(bn * BN) * BYTE_DIM;

    #pragma unroll
    for (int i = 0; i < 16; ++i) {
        int f = tid + i * 256;
        int k = f & 127;
        int r = f >> 7;
        As[k][r] = A [(size_t)r * BYTE_DIM + k];
        Ws[k][r] = Wt[(size_t)r * BYTE_DIM + k];
    }
    __syncthreads();

    float acc[2][2] = {};
    #pragma unroll 8
    for (int k = 0; k < BYTE_DIM; ++k) {
        float a0 = As[k][m0], a1 = As[k][m0 + 1];
        float w0 = Ws[k][n0], w1 = Ws[k][n0 + 1];
        acc[0][0] = fmaf(a0, w0, acc[0][0]);
        acc[0][1] = fmaf(a0, w1, acc[0][1]);
        acc[1][0] = fmaf(a1, w0, acc[1][0]);
        acc[1][1] = fmaf(a1, w1, acc[1][1]);
    }

    #pragma unroll
    for (int i = 0; i < 2; ++i) {
        float2 v = make_float2(acc[i][0] * SCALE_F, acc[i][1] * SCALE_F);
        *reinterpret_cast<float2*>(
            g_proj + (size_t)(bm * BM + m0 + i) * EMB_DIM + bn * BN + n0) = v;
    }
}

// ---------------------------------------------------------------------------
// Kernel 2: ragged mean with SMEM-staged proj slice, quarter-warp per token.
// Tile = 32 channels (8 float4): smem slice [NUM_EMB][8] f4 = 48 KB
//   -> 4 CTAs/SM, 64 warps/SM (full occupancy).
// Each warp processes 4 tokens concurrently (lanes 0-7 tok A, 8-15 tok B, ...)
//   -> 4 independent accumulate chains; LDS.128 wavefront (8 consecutive
//      lanes) reads one contiguous 128B proj row slice: conflict-free.
// Grid (tsplit=2, ch_tile=32, batch=8) = 512 blocks = one full wave.
// ---------------------------------------------------------------------------
#define TILE_F4       8                     // 32 channels per tile
#define POOL_THREADS  512                   // 16 warps
#define TOK_SPLIT     2
#define TOK_PER_BLK   (NUM_TOK / TOK_SPLIT) // 1024
#define TOK_PER_WARP  (TOK_PER_BLK / 16)    // 64
#define GROUPS        (TOK_PER_WARP / 4)    // 16

__global__ __launch_bounds__(POOL_THREADS) void pool_kernel(const int* __restrict__ x,
                                                            float* __restrict__ out) {
    __shared__ float4 ps[NUM_EMB * TILE_F4];   // 48 KB

    const int tsplit = blockIdx.x;   // 0..1
    const int tile   = blockIdx.y;   // 0..31
    const int b      = blockIdx.z;   // 0..7

    // Stage proj[:, tile*32 .. +32): 384 rows x 8 float4 (3072 f4).
    const float4* __restrict__ gp = reinterpret_cast<const float4*>(g_proj);
    #pragma unroll
    for (int i = threadIdx.x; i < NUM_EMB * TILE_F4; i += POOL_THREADS) {
        int e = i >> 3;
        int c = i & 7;
        ps[i] = gp[(size_t)e * (EMB_DIM / 4) + tile * TILE_F4 + c];
    }
    __syncthreads();

    const int wid  = threadIdx.x >> 5;
    const int lane = threadIdx.x & 31;
    const int q    = lane >> 3;   // quarter-warp id: which of 4 tokens
    const int r    = lane & 7;    // float4 index within the 32-ch tile

    const int* __restrict__ xr = x + (size_t)b * S_BYTES;
    float4* __restrict__ o = reinterpret_cast<float4*>(out);
    const size_t obase = ((size_t)b * NUM_TOK) * (EMB_DIM / 4) + tile * TILE_F4 + r;

    const int tbase = tsplit * TOK_PER_BLK + wid * TOK_PER_WARP;

    for (int g = 0; g < GROUPS; ++g) {
        const int t  = tbase + g * 4 + q;
        int       s  = g_start[b][t];
        const int s1 = g_start[b][t + 1];
        const int cnt = s1 - s;

        float4 acc = make_float4(0.f, 0.f, 0.f, 0.f);
        while (__any_sync(0xffffffffu, s < s1)) {
            if (s < s1) {
                const int e = xr[s];               // same addr within quarter
                float4 v = ps[e * TILE_F4 + r];    // conflict-free LDS.128
                acc.x += v.x; acc.y += v.y; acc.z += v.z; acc.w += v.w;
            }
            ++s;
        }

        const float inv = 1.0f / (float)(cnt > 0 ? cnt : 1);
        acc.x *= inv; acc.y *= inv; acc.z *= inv; acc.w *= inv;
        o[obase + (size_t)t * (EMB_DIM / 4)] = acc;
    }
}

// ---------------------------------------------------------------------------
// Launch
// ---------------------------------------------------------------------------
extern "C" void kernel_launch(void* const* d_in, const int* in_sizes, int n_in,
                              void* d_out, int out_size) {
    const int*   x    = (const int*)  d_in[0];  // [B, S_BYTES] int32
    const int*   bg   = (const int*)  d_in[1];  // [B, S_BYTES] int32 (sorted per row)
    const float* emb  = (const float*)d_in[2];  // [NUM_EMB, BYTE_DIM] fp32
    const float* wout = (const float*)d_in[3];  // [EMB_DIM, BYTE_DIM] fp32
    float* out = (float*)d_out;                 // [B, NUM_TOK, EMB_DIM] fp32

    (void)in_sizes; (void)n_in; (void)out_size;

    prep_kernel<<<GEMM_BLOCKS + SEG_BLOCKS, 256>>>(emb, wout, bg);

    dim3 pgrid(TOK_SPLIT, EMB_DIM / (TILE_F4 * 4), BATCH);  // (2, 32, 8)
    pool_kernel<<<pgrid, POOL_THREADS>>>(x, out);
}

// round 6
// speedup vs baseline: 2.3960x; 2.3960x over previous
#include <cuda_runtime.h>
#include <cuda_fp16.h>

// Problem constants
#define BATCH    8
#define S_BYTES  8192
#define NUM_EMB  384
#define BYTE_DIM 128
#define EMB_DIM  1024
#define NUM_TOK  2048
#define SCALE_F  11.313708498984761f  // sqrt(128)

// proj = SCALE * emb @ W^T, stored fp16: [NUM_EMB, EMB_DIM] (768 KB, L2-resident)
__device__ __half g_proj_h[NUM_EMB * EMB_DIM];
// Segment starts: g_start[b][t] = first byte index s with byte_groups[b][s] >= t
__device__ int g_start[BATCH][NUM_TOK + 1];

// ---------------------------------------------------------------------------
// Kernel 1 (fused): blocks [0,384) tiny GEMM proj = SCALE*emb@W^T (fp32 math,
// fp16 store), blocks [384,640) segment boundaries from sorted byte_groups.
// ---------------------------------------------------------------------------
#define BM 32
#define BN 32
#define SPITCH 33
#define GEMM_BLOCKS 384
#define SEG_BLOCKS  256

__global__ __launch_bounds__(256) void prep_kernel(const float* __restrict__ emb,
                                                   const float* __restrict__ W,
                                                   const int* __restrict__ bg) {
    const int tid = threadIdx.x;

    if (blockIdx.x >= GEMM_BLOCKS) {
        // ---- segment boundaries ----
        const int blkk = blockIdx.x - GEMM_BLOCKS;
        const int b    = blkk >> 5;
        const int s    = (blkk & 31) * 256 + tid;
        const int* __restrict__ row = bg + (size_t)b * S_BYTES;

        const int g  = row[s];
        const int gp = (s == 0) ? -1 : row[s - 1];
        for (int t = gp + 1; t <= g; ++t) g_start[b][t] = s;
        if (s == S_BYTES - 1) {
            for (int t = g + 1; t <= NUM_TOK; ++t) g_start[b][t] = S_BYTES;
        }
        return;
    }

    // ---- tiny GEMM: 32x32 tile, full K in smem, one sync ----
    __shared__ float As[BYTE_DIM][SPITCH];  // [k][m]
    __shared__ float Ws[BYTE_DIM][SPITCH];  // [k][n]

    const int bn = blockIdx.x & 31;
    const int bm = blockIdx.x >> 5;
    const int tx = tid & 15;
    const int ty = tid >> 4;
    const int m0 = ty * 2;
    const int n0 = tx * 2;

    const float* __restrict__ A  = emb + (size_t)(bm * BM) * BYTE_DIM;
    const float* __restrict__ Wt = W   + (size_t)(bn * BN) * BYTE_DIM;

    #pragma unroll
    for (int i = 0; i < 16; ++i) {
        int f = tid + i * 256;
        int k = f & 127;
        int r = f >> 7;
        As[k][r] = A [(size_t)r * BYTE_DIM + k];
        Ws[k][r] = Wt[(size_t)r * BYTE_DIM + k];
    }
    __syncthreads();

    float acc[2][2] = {};
    #pragma unroll 8
    for (int k = 0; k < BYTE_DIM; ++k) {
        float a0 = As[k][m0], a1 = As[k][m0 + 1];
        float w0 = Ws[k][n0], w1 = Ws[k][n0 + 1];
        acc[0][0] = fmaf(a0, w0, acc[0][0]);
        acc[0][1] = fmaf(a0, w1, acc[0][1]);
        acc[1][0] = fmaf(a1, w0, acc[1][0]);
        acc[1][1] = fmaf(a1, w1, acc[1][1]);
    }

    #pragma unroll
    for (int i = 0; i < 2; ++i) {
        __half2 h = __floats2half2_rn(acc[i][0] * SCALE_F, acc[i][1] * SCALE_F);
        *reinterpret_cast<__half2*>(
            g_proj_h + (size_t)(bm * BM + m0 + i) * EMB_DIM + bn * BN + n0) = h;
    }
}

// ---------------------------------------------------------------------------
// Kernel 2: ragged mean over fp16 proj rows, warp-per-token (round-3 winner
// structure, halved gather traffic).
// out[b,t,:] = (1/cnt) * sum_{s in [start,end)} proj[x[b,s], :]
// grid = (NUM_TOK/8, BATCH), block = 256 (8 warps). Lane j-loop owns uint2
// (4 halves = 4 channels) at index lane+32j: coalesced LDG.64 gather wave-
// fronts AND perfectly coalesced float4 output stores at the same index.
// Accumulation in fp32.
// ---------------------------------------------------------------------------
__global__ __launch_bounds__(256) void pool_kernel(const int* __restrict__ x,
                                                   float* __restrict__ out) {
    const int b    = blockIdx.y;
    const int wid  = threadIdx.x >> 5;
    const int lane = threadIdx.x & 31;
    const int t    = blockIdx.x * 8 + wid;

    const int s0 = g_start[b][t];
    const int s1 = g_start[b][t + 1];

    const int* __restrict__ xr = x + (size_t)b * S_BYTES;
    const uint2* __restrict__ p = reinterpret_cast<const uint2*>(g_proj_h);  // 512/row

    float4 acc[8];
    #pragma unroll
    for (int j = 0; j < 8; ++j) acc[j] = make_float4(0.f, 0.f, 0.f, 0.f);

    for (int s = s0; s < s1; ++s) {
        const int e = xr[s];  // warp-broadcast load
        const uint2* __restrict__ pr = p + (size_t)e * (EMB_DIM / 4);
        #pragma unroll
        for (int j = 0; j < 8; ++j) {
            uint2 u = pr[lane + 32 * j];  // coalesced 256B wavefront, L2-hit
            __half2 h0 = *reinterpret_cast<__half2*>(&u.x);
            __half2 h1 = *reinterpret_cast<__half2*>(&u.y);
            float2 f0 = __half22float2(h0);
            float2 f1 = __half22float2(h1);
            acc[j].x += f0.x; acc[j].y += f0.y;
            acc[j].z += f1.x; acc[j].w += f1.y;
        }
    }

    const int cnt = s1 - s0;
    const float inv = 1.0f / (float)(cnt > 0 ? cnt : 1);

    float4* __restrict__ o =
        reinterpret_cast<float4*>(out) + (((size_t)b * NUM_TOK) + t) * (EMB_DIM / 4);
    #pragma unroll
    for (int j = 0; j < 8; ++j) {
        float4 v = make_float4(acc[j].x * inv, acc[j].y * inv,
                               acc[j].z * inv, acc[j].w * inv);
        o[lane + 32 * j] = v;  // coalesced STG.128
    }
}

// ---------------------------------------------------------------------------
// Launch
// ---------------------------------------------------------------------------
extern "C" void kernel_launch(void* const* d_in, const int* in_sizes, int n_in,
                              void* d_out, int out_size) {
    const int*   x    = (const int*)  d_in[0];  // [B, S_BYTES] int32
    const int*   bg   = (const int*)  d_in[1];  // [B, S_BYTES] int32 (sorted per row)
    const float* emb  = (const float*)d_in[2];  // [NUM_EMB, BYTE_DIM] fp32
    const float* wout = (const float*)d_in[3];  // [EMB_DIM, BYTE_DIM] fp32
    float* out = (float*)d_out;                 // [B, NUM_TOK, EMB_DIM] fp32

    (void)in_sizes; (void)n_in; (void)out_size;

    prep_kernel<<<GEMM_BLOCKS + SEG_BLOCKS, 256>>>(emb, wout, bg);

    dim3 pgrid(NUM_TOK / 8, BATCH);             // (256, 8) = 2048 blocks
    pool_kernel<<<pgrid, 256>>>(x, out);
}